// round 16
// baseline (speedup 1.0000x reference)
#include <cuda_runtime.h>
#include <cuda_fp16.h>

// ---------------------------------------------------------------------------
// 3-layer GCN. R16: agg1+gemm2 and agg2+gemm3 FUSED (agg is row-local w.r.t.
// the following GEMM): block aggregates its 64 nodes into an smem A-tile,
// syncs once, then runs the full-K MMA sweep with W^T fully smem-resident.
// Kills the g_a round-trip (77MB L2) + 2 launch tails. Same rounding points
// -> rel_err bit-identical. gemm1 (slot 4) + preproc fork from R15 retained.
// ---------------------------------------------------------------------------

#define NN 100000
#define NE 1600000
#define IN_C 256
#define H1C 128
#define H2C 64
#define OUTC 32

__device__ int    g_cnt[NN];
__device__ int    g_cursor[NN];
__device__ int    g_off[NN];
__device__ int    g_bsum[128];
__device__ float  g_dis[NN];
__device__ int    g_esrc[NE];
__device__ float  g_enorm[NE];
__device__ __half g_h[(size_t)NN * 128];   // layer buffer A (fp16)
__device__ __half g_a[(size_t)NN * 128];   // layer buffer B (fp16)
__device__ __half g_w1t[IN_C * H1C];       // W1^T fp16 [128][256]
__device__ __half g_w2t[H1C * H2C];        // W2^T fp16 [64][128]
__device__ __half g_w3t[H2C * OUTC];       // W3^T fp16 [32][64]

// ---------------------------------------------------------------------------
// W prep: W[K,N] fp32 row-major -> Wt[N,K] fp16
// ---------------------------------------------------------------------------
template <int N, int K>
__global__ void k_wprep(const float* __restrict__ W, __half* __restrict__ Wt) {
    int idx = blockIdx.x * blockDim.x + threadIdx.x;
    if (idx >= N * K) return;
    int n = idx / K, k = idx % K;
    Wt[idx] = __float2half_rn(W[(size_t)k * N + n]);
}

// ---------------------------------------------------------------------------
// graph preprocessing
// ---------------------------------------------------------------------------
__global__ void k_zero(int n) {
    int i = blockIdx.x * blockDim.x + threadIdx.x;
    if (i < n) g_cnt[i] = 0;
}
__global__ void k_count(const int* __restrict__ col, int e_cnt) {
    int e = blockIdx.x * blockDim.x + threadIdx.x;
    if (e < e_cnt) atomicAdd(&g_cnt[col[e]], 1);
}
__global__ void k_scan1(int n) {
    __shared__ int s[1024];
    int i = blockIdx.x * 1024 + threadIdx.x;
    int v = (i < n) ? g_cnt[i] : 0;
    if (i < n) g_dis[i] = rsqrtf((float)v + 1.0f);
    s[threadIdx.x] = v;
    __syncthreads();
    #pragma unroll
    for (int off = 1; off < 1024; off <<= 1) {
        int t = (threadIdx.x >= off) ? s[threadIdx.x - off] : 0;
        __syncthreads();
        s[threadIdx.x] += t;
        __syncthreads();
    }
    if (i < n) g_off[i] = s[threadIdx.x];
    if (threadIdx.x == 1023) g_bsum[blockIdx.x] = s[1023];
}
__global__ void k_scan3(int n, int nb) {
    __shared__ int pref[128];
    int t = threadIdx.x;
    int v = (t < 128 && t < nb) ? g_bsum[t] : 0;
    if (t < 128) pref[t] = v;
    __syncthreads();
    #pragma unroll
    for (int off = 1; off < 128; off <<= 1) {
        int u = (t < 128 && t >= off) ? pref[t - off] : 0;
        __syncthreads();
        if (t < 128) pref[t] += u;
        __syncthreads();
    }
    int i = blockIdx.x * blockDim.x + t;
    if (i < n) {
        int b = i >> 10;
        int boff = pref[b] - g_bsum[b];
        int off = g_off[i] - g_cnt[i] + boff;
        g_off[i] = off;
        g_cursor[i] = off;
    }
}
__global__ void k_scatter(const int* __restrict__ row, const int* __restrict__ col, int e_cnt) {
    int e = blockIdx.x * blockDim.x + threadIdx.x;
    if (e >= e_cnt) return;
    int r = row[e], c = col[e];
    int pos = atomicAdd(&g_cursor[c], 1);
    g_esrc[pos]  = r;
    g_enorm[pos] = g_dis[r] * g_dis[c];
}

// ---------------------------------------------------------------------------
// shared helpers
// ---------------------------------------------------------------------------
__device__ __forceinline__ void mma_f16(float* c, const unsigned* a, const unsigned* b) {
    asm volatile(
        "mma.sync.aligned.m16n8k16.row.col.f32.f16.f16.f32 "
        "{%0,%1,%2,%3},{%4,%5,%6,%7},{%8,%9},{%0,%1,%2,%3};"
        : "+f"(c[0]), "+f"(c[1]), "+f"(c[2]), "+f"(c[3])
        : "r"(a[0]), "r"(a[1]), "r"(a[2]), "r"(a[3]), "r"(b[0]), "r"(b[1]));
}

template <int VEC>
__device__ __forceinline__ void loadh(float* d, const __half* __restrict__ p) {
    if constexpr (VEC == 4) {
        uint2 raw = __ldg(reinterpret_cast<const uint2*>(p));
        float2 a = __half22float2(*reinterpret_cast<const __half2*>(&raw.x));
        float2 b = __half22float2(*reinterpret_cast<const __half2*>(&raw.y));
        d[0] = a.x; d[1] = a.y; d[2] = b.x; d[3] = b.y;
    } else if constexpr (VEC == 2) {
        __half2 h2 = __ldg(reinterpret_cast<const __half2*>(p));
        float2 a = __half22float2(h2);
        d[0] = a.x; d[1] = a.y;
    } else {
        d[0] = __half2float(__ldg(p));
    }
}

// aggregate one node into acc[VEC] (self-loop + CSR edges + bias [+relu])
template <int F, bool RELU>
__device__ __forceinline__ void agg_node(int node, const __half* __restrict__ h,
                                         const float* __restrict__ bias, int lane,
                                         float* res) {
    constexpr int VEC = F / 32;
    float acc[VEC];
    {
        float d = g_dis[node];
        float ns = d * d;
        float t[VEC];
        loadh<VEC>(t, h + (size_t)node * F + lane * VEC);
        #pragma unroll
        for (int v = 0; v < VEC; v++) acc[v] = ns * t[v];
    }
    int start = g_off[node];
    int cnt   = g_cnt[node];
    int e = start, end = start + cnt;

    for (; e + 8 <= end; e += 8) {
        int   s[8];
        float nm[8];
        #pragma unroll
        for (int j = 0; j < 8; j++) { s[j] = g_esrc[e + j]; nm[j] = g_enorm[e + j]; }
        float t[8][VEC];
        #pragma unroll
        for (int j = 0; j < 8; j++)
            loadh<VEC>(t[j], h + (size_t)s[j] * F + lane * VEC);
        #pragma unroll
        for (int j = 0; j < 8; j++)
            #pragma unroll
            for (int v = 0; v < VEC; v++) acc[v] += nm[j] * t[j][v];
    }
    for (; e + 4 <= end; e += 4) {
        int   s[4];
        float nm[4];
        #pragma unroll
        for (int j = 0; j < 4; j++) { s[j] = g_esrc[e + j]; nm[j] = g_enorm[e + j]; }
        float t[4][VEC];
        #pragma unroll
        for (int j = 0; j < 4; j++)
            loadh<VEC>(t[j], h + (size_t)s[j] * F + lane * VEC);
        #pragma unroll
        for (int j = 0; j < 4; j++)
            #pragma unroll
            for (int v = 0; v < VEC; v++) acc[v] += nm[j] * t[j][v];
    }
    for (; e < end; e++) {
        int s0 = g_esrc[e];
        float nm = g_enorm[e];
        float t[VEC];
        loadh<VEC>(t, h + (size_t)s0 * F + lane * VEC);
        #pragma unroll
        for (int v = 0; v < VEC; v++) acc[v] += nm * t[v];
    }
    #pragma unroll
    for (int v = 0; v < VEC; v++) {
        float r = acc[v] + bias[lane * VEC + v];
        if (RELU) r = fmaxf(r, 0.0f);
        res[v] = r;
    }
}

// ---------------------------------------------------------------------------
// FUSED agg+gemm: block aggregates 64 nodes (gather width K) into smem,
// then C[M,N] = At @ Wt with W^T fully smem-resident. One sync.
// ---------------------------------------------------------------------------
template <int K, int N>
__launch_bounds__(256)
__global__ void k_agg_gemm(const __half* __restrict__ hsrc, const float* __restrict__ bias,
                           const __half* __restrict__ Wt, __half* __restrict__ C, int M) {
    constexpr int VEC = K / 32;        // 4 (K=128) / 2 (K=64)
    constexpr int SA = K + 8;
    constexpr int WN = N / 4;          // 16 / 8
    constexpr int NT = WN / 8;         // 2 / 1
    constexpr int WUNITS = N * K / 8;  // 1024 / 256 (multiples of 256)

    __shared__ __align__(16) __half At[64 * SA];
    __shared__ __align__(16) __half Wsh[N * SA];

    int tid = threadIdx.x;
    int lane = tid & 31, warp = tid >> 5;
    int g = lane >> 2, tg = lane & 3;
    int m0 = blockIdx.x * 64;

    // ---- load full W^T tile into smem ----
    #pragma unroll
    for (int i = 0; i < WUNITS / 256; i++) {
        int u = tid + i * 256;
        int n = u / (K / 8), seg = u % (K / 8);
        *reinterpret_cast<uint4*>(Wsh + n * SA + seg * 8) =
            *reinterpret_cast<const uint4*>(Wt + (size_t)n * K + seg * 8);
    }

    // ---- agg phase: warp w aggregates nodes m0+8w .. m0+8w+7 into At ----
    for (int i = 0; i < 8; i++) {
        int node = m0 + warp * 8 + i;
        if (node >= NN) break;                       // warp-uniform
        float res[VEC];
        agg_node<K, true>(node, hsrc, bias, lane, res);
        __half* op = At + (warp * 8 + i) * SA + lane * VEC;
        if constexpr (VEC == 4) {
            __half2 p0 = __floats2half2_rn(res[0], res[1]);
            __half2 p1 = __floats2half2_rn(res[2], res[3]);
            *reinterpret_cast<uint2*>(op) =
                make_uint2(*reinterpret_cast<unsigned*>(&p0), *reinterpret_cast<unsigned*>(&p1));
        } else {
            *reinterpret_cast<__half2*>(op) = __floats2half2_rn(res[0], res[1]);
        }
    }
    __syncthreads();

    // ---- gemm phase: full-K LDS+MMA sweep ----
    int wm = (warp & 1) * 32;
    int wn = (warp >> 1) * WN;
    float acc[2][NT][4] = {};
    #pragma unroll
    for (int kk = 0; kk < K; kk += 16) {
        unsigned a[2][4];
        #pragma unroll
        for (int mt = 0; mt < 2; mt++) {
            int base = (wm + mt * 16 + g) * SA + kk + tg * 2;
            a[mt][0] = *reinterpret_cast<const unsigned*>(At + base);
            a[mt][1] = *reinterpret_cast<const unsigned*>(At + base + 8 * SA);
            a[mt][2] = *reinterpret_cast<const unsigned*>(At + base + 8);
            a[mt][3] = *reinterpret_cast<const unsigned*>(At + base + 8 * SA + 8);
        }
        #pragma unroll
        for (int nt = 0; nt < NT; nt++) {
            int bb = (wn + nt * 8 + g) * SA + kk + tg * 2;
            unsigned b[2];
            b[0] = *reinterpret_cast<const unsigned*>(Wsh + bb);
            b[1] = *reinterpret_cast<const unsigned*>(Wsh + bb + 8);
            #pragma unroll
            for (int mt = 0; mt < 2; mt++)
                mma_f16(acc[mt][nt], a[mt], b);
        }
    }

    #pragma unroll
    for (int mt = 0; mt < 2; mt++) {
        #pragma unroll
        for (int nt = 0; nt < NT; nt++) {
            int row0 = m0 + wm + mt * 16 + g;
            int col = wn + nt * 8 + 2 * tg;
            if (row0 < M)
                *reinterpret_cast<__half2*>(C + (size_t)row0 * N + col) =
                    __floats2half2_rn(acc[mt][nt][0], acc[mt][nt][1]);
            int row1 = row0 + 8;
            if (row1 < M)
                *reinterpret_cast<__half2*>(C + (size_t)row1 * N + col) =
                    __floats2half2_rn(acc[mt][nt][2], acc[mt][nt][3]);
        }
    }
}

// ---------------------------------------------------------------------------
// gemm1 (R15): double-buffered, 2-tile lookahead, pre-transposed fp16 W
// ---------------------------------------------------------------------------
template <typename AT, int N, int K>
__launch_bounds__(256, 2)
__global__ void k_gemm(const AT* __restrict__ A, const __half* __restrict__ Wt,
                       __half* __restrict__ C, int M) {
    constexpr bool A16 = (sizeof(AT) == 2);
    constexpr int BM = 64, BK = 32;
    constexpr int SA = BK + 8;
    constexpr int SW = BK + 8;
    constexpr int WM = 32;
    constexpr int WN = N / 4;
    constexpr int MT = 2;
    constexpr int NT = WN / 8;
    constexpr int ABUF = BM * SA;
    constexpr int WBUF = N * SW;
    constexpr int WUNITS = N * 4;
    constexpr int WLOC = (WUNITS + 255) / 256;

    __shared__ __align__(16) __half As[2 * ABUF];
    __shared__ __align__(16) __half Ws[2 * WBUF];

    int tid = threadIdx.x;
    int lane = tid & 31, warp = tid >> 5;
    int wm = (warp & 1) * WM;
    int wn = (warp >> 1) * WN;
    int m0 = blockIdx.x * BM;
    int g = lane >> 2, tg = lane & 3;

    float acc[MT][NT][4] = {};

    int a_r[2], a_c[2];
    #pragma unroll
    for (int i = 0; i < 2; i++) {
        int idx = tid + i * 256;
        a_r[i] = idx >> 3;
        a_c[i] = idx & 7;
    }
    bool arow_ok[2];
    #pragma unroll
    for (int i = 0; i < 2; i++) arow_ok[i] = (m0 + a_r[i]) < M;

    float4 aRegF[2];
    uint2  aRegH[2];
    uint4  wReg[WLOC];

    auto loadA = [&](int kb) {
        #pragma unroll
        for (int i = 0; i < 2; i++) {
            int m = m0 + a_r[i];
            if (A16) {
                aRegH[i] = make_uint2(0u, 0u);
                if (arow_ok[i])
                    aRegH[i] = *reinterpret_cast<const uint2*>(
                        reinterpret_cast<const __half*>(A) + (size_t)m * K + kb + a_c[i] * 4);
            } else {
                aRegF[i] = make_float4(0.f, 0.f, 0.f, 0.f);
                if (arow_ok[i])
                    aRegF[i] = *reinterpret_cast<const float4*>(
                        reinterpret_cast<const float*>(A) + (size_t)m * K + kb + a_c[i] * 4);
            }
        }
    };
    auto loadW = [&](int kb) {
        #pragma unroll
        for (int i = 0; i < WLOC; i++) {
            int u = tid + i * 256;
            if (WUNITS >= 256 || u < WUNITS) {
                int n = u >> 2, seg = u & 3;
                wReg[i] = *reinterpret_cast<const uint4*>(Wt + (size_t)n * K + kb + seg * 8);
            }
        }
    };
    auto commit = [&](int buf) {
        __half* Ab = As + buf * ABUF;
        __half* Wb = Ws + buf * WBUF;
        #pragma unroll
        for (int i = 0; i < 2; i++) {
            uint2 u;
            if (A16) {
                u = aRegH[i];
            } else {
                __half2 p0 = __floats2half2_rn(aRegF[i].x, aRegF[i].y);
                __half2 p1 = __floats2half2_rn(aRegF[i].z, aRegF[i].w);
                u = make_uint2(*reinterpret_cast<unsigned*>(&p0),
                               *reinterpret_cast<unsigned*>(&p1));
            }
            *reinterpret_cast<uint2*>(Ab + a_r[i] * SA + a_c[i] * 4) = u;
        }
        #pragma unroll
        for (int i = 0; i < WLOC; i++) {
            int u = tid + i * 256;
            if (WUNITS >= 256 || u < WUNITS) {
                int n = u >> 2, seg = u & 3;
                *reinterpret_cast<uint4*>(Wb + n * SW + seg * 8) = wReg[i];
            }
        }
    };

    loadA(0); loadW(0);
    commit(0);
    if (BK < K) { loadA(BK); loadW(BK); }

    int cur = 0;
    for (int k0 = 0; k0 < K; k0 += BK) {
        __syncthreads();
        int kn = k0 + BK;
        if (kn < K) commit(cur ^ 1);
        int kp = k0 + 2 * BK;
        if (kp < K) { loadA(kp); loadW(kp); }

        const __half* Ab = As + cur * ABUF;
        const __half* Wb = Ws + cur * WBUF;
        #pragma unroll
        for (int kk = 0; kk < BK; kk += 16) {
            unsigned a[MT][4];
            #pragma unroll
            for (int mt = 0; mt < MT; mt++) {
                int base = (wm + mt * 16 + g) * SA + kk + tg * 2;
                a[mt][0] = *reinterpret_cast<const unsigned*>(Ab + base);
                a[mt][1] = *reinterpret_cast<const unsigned*>(Ab + base + 8 * SA);
                a[mt][2] = *reinterpret_cast<const unsigned*>(Ab + base + 8);
                a[mt][3] = *reinterpret_cast<const unsigned*>(Ab + base + 8 * SA + 8);
            }
            #pragma unroll
            for (int nt = 0; nt < NT; nt++) {
                int bb = (wn + nt * 8 + g) * SW + kk + tg * 2;
                unsigned b[2];
                b[0] = *reinterpret_cast<const unsigned*>(Wb + bb);
                b[1] = *reinterpret_cast<const unsigned*>(Wb + bb + 8);
                #pragma unroll
                for (int mt = 0; mt < MT; mt++)
                    mma_f16(acc[mt][nt], a[mt], b);
            }
        }
        cur ^= 1;
    }

    #pragma unroll
    for (int mt = 0; mt < MT; mt++) {
        #pragma unroll
        for (int nt = 0; nt < NT; nt++) {
            int row0 = m0 + wm + mt * 16 + g;
            int col = wn + nt * 8 + 2 * tg;
            if (row0 < M)
                *reinterpret_cast<__half2*>(C + (size_t)row0 * N + col) =
                    __floats2half2_rn(acc[mt][nt][0], acc[mt][nt][1]);
            int row1 = row0 + 8;
            if (row1 < M)
                *reinterpret_cast<__half2*>(C + (size_t)row1 * N + col) =
                    __floats2half2_rn(acc[mt][nt][2], acc[mt][nt][3]);
        }
    }
}

// ---------------------------------------------------------------------------
// final standalone aggregation (layer 3): fp32 output
// ---------------------------------------------------------------------------
template <int F, bool RELU>
__launch_bounds__(256)
__global__ void k_agg(const __half* __restrict__ h, const float* __restrict__ bias,
                      float* __restrict__ out) {
    constexpr int VEC = F / 32;
    int node = (blockIdx.x * blockDim.x + threadIdx.x) >> 5;
    int lane = threadIdx.x & 31;
    if (node >= NN) return;
    float res[VEC];
    agg_node<F, RELU>(node, h, bias, lane, res);
    float* op = out + (size_t)node * F + lane * VEC;
    if constexpr (VEC == 4)
        *reinterpret_cast<float4*>(op) = make_float4(res[0], res[1], res[2], res[3]);
    else if constexpr (VEC == 2)
        *reinterpret_cast<float2*>(op) = make_float2(res[0], res[1]);
    else
        *op = res[0];
}

// ---------------------------------------------------------------------------
extern "C" void kernel_launch(void* const* d_in, const int* in_sizes, int n_in,
                              void* d_out, int out_size) {
    const float* x  = (const float*)d_in[0];
    const int*   ei = (const int*)d_in[1];
    const float* W1 = (const float*)d_in[2];
    const float* b1 = (const float*)d_in[3];
    const float* W2 = (const float*)d_in[4];
    const float* b2 = (const float*)d_in[5];
    const float* W3 = (const float*)d_in[6];
    const float* b3 = (const float*)d_in[7];

    int M = in_sizes[0] / IN_C;   // 100000
    int E = in_sizes[1] / 2;      // 1600000
    const int* row = ei;          // sources
    const int* col = ei + E;      // targets
    float* out = (float*)d_out;

    __half *gh, *ga, *w1t, *w2t, *w3t;
    cudaGetSymbolAddress((void**)&gh, g_h);
    cudaGetSymbolAddress((void**)&ga, g_a);
    cudaGetSymbolAddress((void**)&w1t, g_w1t);
    cudaGetSymbolAddress((void**)&w2t, g_w2t);
    cudaGetSymbolAddress((void**)&w3t, g_w3t);

    static cudaStream_t s2 = nullptr;
    static cudaEvent_t evFork = nullptr, evJoin = nullptr;
    if (s2 == nullptr) {
        cudaStreamCreateWithFlags(&s2, cudaStreamNonBlocking);
        cudaEventCreateWithFlags(&evFork, cudaEventDisableTiming);
        cudaEventCreateWithFlags(&evJoin, cudaEventDisableTiming);
    }

    int nb1024 = (M + 1023) / 1024;
    int aggBlocks = (M + 7) / 8;
    int gemmBlocks = (M + 63) / 64;
    int fusedBlocks = (M + 63) / 64;

    // ---- fork ----
    cudaEventRecord(evFork, 0);
    cudaStreamWaitEvent(s2, evFork, 0);

    // gemm1 in ncu slot 4
    k_wprep<H1C, IN_C><<<(IN_C * H1C + 255) / 256, 256>>>(W1, w1t);         // 1 (main)
    k_zero <<<(M + 255) / 256, 256, 0, s2>>>(M);                            // 2
    k_count<<<(E + 255) / 256, 256, 0, s2>>>(col, E);                       // 3
    k_gemm<float, H1C, IN_C><<<gemmBlocks, 256>>>(x, w1t, gh, M);           // 4 <- profiled
    k_scan1  <<<nb1024, 1024, 0, s2>>>(M);                                  // 5
    k_scan3  <<<(M + 255) / 256, 256, 0, s2>>>(M, nb1024);                  // 6
    k_scatter<<<(E + 255) / 256, 256, 0, s2>>>(row, col, E);                // 7
    k_wprep<H2C, H1C> <<<(H1C * H2C + 255) / 256, 256, 0, s2>>>(W2, w2t);   // 8
    k_wprep<OUTC, H2C><<<(H2C * OUTC + 255) / 256, 256, 0, s2>>>(W3, w3t);  // 9
    cudaEventRecord(evJoin, s2);

    cudaStreamWaitEvent(0, evJoin, 0);

    // fused agg1+gemm2: gather g_h (F=128), gemm N=64 -> g_a
    k_agg_gemm<H1C, H2C><<<fusedBlocks, 256>>>(gh, b1, w2t, ga, M);
    // fused agg2+gemm3: gather g_a (F=64), gemm N=32 -> g_h
    k_agg_gemm<H2C, OUTC><<<fusedBlocks, 256>>>(ga, b2, w3t, gh, M);
    // final agg3: gather g_h (F=32) -> out fp32
    k_agg<OUTC, false><<<aggBlocks, 256>>>(gh, b3, out);
}